// round 13
// baseline (speedup 1.0000x reference)
#include <cuda_runtime.h>
#include <cuda_bf16.h>

#define NN      65536
#define NE      1048576
#define NG      64
#define NPG     1024
#define CF      8
#define RSTRIDE 64      // edge slots per node

typedef unsigned long long ull;

__device__ int   g_deg[NN];
__device__ int   g_cnt[NN];
__device__ int   g_cur[NN];
// interleave: [(node/8)][slot/2][node%8][slot%2] -> per sub-lane, slot pair = 16B
__device__ __align__(16) int2 g_edges[(size_t)NN * RSTRIDE];
__device__ float g_tx[640ull * NN];
__device__ float g_ha[(size_t)NN * 64];
__device__ float g_hb[(size_t)NN * 64];

__device__ __forceinline__ ull pack2(float x, float y) {
    ull r; asm("mov.b64 %0, {%1, %2};" : "=l"(r) : "f"(x), "f"(y)); return r;
}
__device__ __forceinline__ void ffma2(ull& d, ull a, ull b) {
    asm("fma.rn.f32x2 %0, %1, %2, %0;" : "+l"(d) : "l"(a), "l"(b));
}
__device__ __forceinline__ void unpack2(ull v, float& x, float& y) {
    asm("mov.b64 {%0, %1}, %2;" : "=f"(x), "=f"(y) : "l"(v));
}

// ---------------- prep ----------------
// Tail-of-launch reset; __device__ arrays are zero at load, replays re-zero.
__global__ void zero_kernel() {
    int i = blockIdx.x * blockDim.x + threadIdx.x;
    if (i < NN) { g_deg[i] = 0; g_cnt[i] = 0; g_cur[i] = 0; }
}

__global__ void deg_kernel(const int* __restrict__ ei) {
    int e = blockIdx.x * blockDim.x + threadIdx.x;
    if (e >= NE) return;
    int s = ei[e], d = ei[NE + e];
    if (s != d) { atomicAdd(&g_deg[s], 1); atomicAdd(&g_cnt[d], 1); }
}

__global__ void fill_kernel(const int* __restrict__ ei,
                            const float* __restrict__ lam) {
    int e = blockIdx.x * blockDim.x + threadIdx.x;
    if (e >= NE) return;
    int s = ei[e], d = ei[NE + e];
    if (s == d) return;
    int od = g_deg[d];
    float dd = (od > 0) ? rsqrtf((float)od) : 0.0f;
    float w = -2.0f * rsqrtf((float)g_deg[s]) * dd / lam[s >> 10];
    int slot = atomicAdd(&g_cur[d], 1);
    int sloc = s & (NPG - 1);
    int eoff = (sloc << 5) | (((sloc >> 2) & 3) << 3);
    size_t idx = (size_t)(d & ~7) * RSTRIDE
               + (size_t)(slot >> 1) * 16 + (d & 7) * 2 + (slot & 1);
    g_edges[idx] = make_int2(eoff, __float_as_int(w));
}

// ---------------- Chebyshev recurrence (unchanged from R11) ----------------
template<int F>
__global__ void __launch_bounds__(1024, 2)
spmv_kernel(const float* __restrict__ hin, const float* __restrict__ lam,
            float* __restrict__ txout) {
    extern __shared__ float sm[];
    float* buf0 = sm;                   // [1024][8] swizzled
    float* buf1 = sm + NPG * 8;

    const int g = blockIdx.y, cb = blockIdx.x * CF, t = threadIdx.x;
    const int gbase = g * NPG;
    const float diag = 2.0f / lam[g] - 1.0f;

    const float* hp = hin + (size_t)gbase * F + cb;
    #pragma unroll
    for (int r = 0; r < CF; r++) {
        int i = r * 1024 + t;
        int row = i >> 3, f = i & 7;
        int sw = ((f >> 1) ^ ((row >> 2) & 3)) * 2 + (f & 1);
        buf0[row * 8 + sw] = hp[row * F + f];
    }
    __syncthreads();

    {
        int s_t = (t >> 2) & 3;
        #pragma unroll
        for (int f = 0; f < CF; f++) {
            int sw = ((f >> 1) ^ s_t) * 2 + (f & 1);
            txout[(size_t)(cb + f) * NN + gbase + t] = buf0[t * 8 + sw];
        }
    }

    const int lane = t & 31, warp = t >> 5;
    const int fp8 = (lane & 3) * 8;
    const int sub = lane >> 2;
    int v = g_cnt[gbase + warp * 32 + lane];
    v = max(v, __shfl_xor_sync(0xffffffffu, v, 1));
    v = max(v, __shfl_xor_sync(0xffffffffu, v, 2));
    v = max(v, __shfl_xor_sync(0xffffffffu, v, 4));

    float* cur = buf0; float* oth = buf1;
    for (int k = 1; k < 5; k++) {
        const char* curb = (const char*)cur;
        #pragma unroll 1
        for (int p = 0; p < 4; p++) {
            const int gdeg = __shfl_sync(0xffffffffu, v, p * 8);
            const int node8 = warp * 32 + p * 8;
            const char* ebase =
                (const char*)(g_edges + (size_t)(gbase + node8) * RSTRIDE) + sub * 16;
            float ax = 0.0f, ay = 0.0f;
            #pragma unroll 1
            for (int i = 0; i < gdeg; i += 4) {
                int4 E0 = *(const int4*)(ebase + (size_t)i * 64);
                int4 E1 = *(const int4*)(ebase + (size_t)i * 64 + 128);
                float2 v0 = *(const float2*)(curb + (E0.x ^ fp8));
                float2 v1 = *(const float2*)(curb + (E0.z ^ fp8));
                float2 v2 = *(const float2*)(curb + (E1.x ^ fp8));
                float2 v3 = *(const float2*)(curb + (E1.z ^ fp8));
                float w0 = __int_as_float(E0.y), w1 = __int_as_float(E0.w);
                float w2 = __int_as_float(E1.y), w3 = __int_as_float(E1.w);
                ax = fmaf(w0, v0.x, ax); ay = fmaf(w0, v0.y, ay);
                ax = fmaf(w1, v1.x, ax); ay = fmaf(w1, v1.y, ay);
                ax = fmaf(w2, v2.x, ax); ay = fmaf(w2, v2.y, ay);
                ax = fmaf(w3, v3.x, ax); ay = fmaf(w3, v3.y, ay);
            }
            const int dloc = node8 + sub;
            const int swb = fp8 ^ (((dloc >> 2) & 3) << 3);
            float2 c = *(const float2*)((const char*)cur + dloc * 32 + swb);
            float lx = fmaf(diag, c.x, ax);
            float ly = fmaf(diag, c.y, ay);
            float2* op = (float2*)((char*)oth + dloc * 32 + swb);
            if (k > 1) { float2 o = *op; lx = 2.0f * lx - o.x; ly = 2.0f * ly - o.y; }
            *op = make_float2(lx, ly);
        }
        __syncthreads();
        int s_t = (t >> 2) & 3;
        #pragma unroll
        for (int f = 0; f < CF; f++) {
            int sw = ((f >> 1) ^ s_t) * 2 + (f & 1);
            txout[(size_t)(k * F + cb + f) * NN + gbase + t] = oth[t * 8 + sw];
        }
        float* tmp = cur; cur = oth; oth = tmp;
        __syncthreads();
    }
}

// ---------------- GEMM v3: occupancy-first ----------------
// out = relu(A^T W + b); A:[K][NN], W:[K][N]. MT nodes/block, TM nodes/thread.
// threads = (MT/TM)*(N/8) = 256 for both configs; grid = NN/MT = 512.
template<int K, int N, int MT, int TM>
__global__ void __launch_bounds__(256)
gemm_kernel(const float* __restrict__ A, const float* __restrict__ W,
            const float* __restrict__ bias, float* __restrict__ out) {
    constexpr int NJG = N / 8;
    constexpr int MG  = MT / TM;
    static_assert(MG * NJG == 256, "cfg");
    __shared__ __align__(16) float As[16 * MT];
    __shared__ __align__(16) float Ws[16 * N];

    const int t = threadIdx.x;
    const int jg = t % NJG, mg = t / NJG;
    const int m0 = blockIdx.x * MT;

    ull acc[TM][4];
    #pragma unroll
    for (int a = 0; a < TM; a++)
        #pragma unroll
        for (int b = 0; b < 4; b++) acc[a][b] = 0ULL;

    for (int k0 = 0; k0 < K; k0 += 16) {
        #pragma unroll
        for (int i = t * 4; i < 16 * MT; i += 1024)
            *(float4*)&As[i] =
                *(const float4*)&A[(size_t)(k0 + i / MT) * NN + m0 + (i % MT)];
        for (int i = t * 4; i < 16 * N; i += 1024)
            *(float4*)&Ws[i] = *(const float4*)&W[(size_t)k0 * N + i];
        __syncthreads();
        #pragma unroll
        for (int kk = 0; kk < 16; kk++) {
            const float* ap = &As[kk * MT + mg * TM];
            const ull* wr = (const ull*)&Ws[kk * N + jg * 8];
            ull w0 = wr[0], w1 = wr[1], w2 = wr[2], w3 = wr[3];
            #pragma unroll
            for (int tt = 0; tt < TM; tt++) {
                float a = ap[tt];
                ull ab = pack2(a, a);
                ffma2(acc[tt][0], ab, w0);
                ffma2(acc[tt][1], ab, w1);
                ffma2(acc[tt][2], ab, w2);
                ffma2(acc[tt][3], ab, w3);
            }
        }
        __syncthreads();
    }

    #pragma unroll
    for (int tt = 0; tt < TM; tt++) {
        size_t node = m0 + mg * TM + tt;
        #pragma unroll
        for (int p = 0; p < 4; p++) {
            float x, y; unpack2(acc[tt][p], x, y);
            int j = jg * 8 + 2 * p;
            x = fmaxf(x + bias[j], 0.0f);
            y = fmaxf(y + bias[j + 1], 0.0f);
            *reinterpret_cast<float2*>(&out[node * N + j]) = make_float2(x, y);
        }
    }
}

// ---------------- pool + FC ----------------
__global__ void pool_fc_kernel(const float* __restrict__ h,
                               const float* __restrict__ fcW1, const float* __restrict__ fcb1,
                               const float* __restrict__ fcW2, const float* __restrict__ fcb2,
                               float* __restrict__ out) {
    __shared__ float red[256];
    __shared__ float pool[64];
    __shared__ float z1[10];
    int g = blockIdx.x, t = threadIdx.x;
    int f = t & 63, part = t >> 6;
    float s = 0.0f;
    for (int n = part; n < NPG; n += 4)
        s += h[(size_t)(g * NPG + n) * 64 + f];
    red[t] = s;
    __syncthreads();
    if (part == 0)
        pool[f] = (red[f] + red[64 + f] + red[128 + f] + red[192 + f]) * (1.0f / NPG);
    __syncthreads();
    if (t < 10) {
        float z = fcb1[t];
        for (int i = 0; i < 64; i++) z += pool[i] * fcW1[i * 10 + t];
        z1[t] = fmaxf(z, 0.0f);
    }
    __syncthreads();
    if (t < 10) {
        float z = fcb2[t];
        for (int j = 0; j < 10; j++) z += z1[j] * fcW2[j * 10 + t];
        out[g * 10 + t] = z;
    }
}

// ---------------- launch ----------------
extern "C" void kernel_launch(void* const* d_in, const int* in_sizes, int n_in,
                              void* d_out, int out_size) {
    const float* x     = (const float*)d_in[0];
    const int*   ei    = (const int*)d_in[1];
    const float* lam   = (const float*)d_in[3];
    const float* W1 = (const float*)d_in[4];  const float* b1 = (const float*)d_in[5];
    const float* W2 = (const float*)d_in[6];  const float* b2 = (const float*)d_in[7];
    const float* W3 = (const float*)d_in[8];  const float* b3 = (const float*)d_in[9];
    const float* fcW1 = (const float*)d_in[10]; const float* fcb1 = (const float*)d_in[11];
    const float* fcW2 = (const float*)d_in[12]; const float* fcb2 = (const float*)d_in[13];
    float* out = (float*)d_out;

    const int SMEM = 2 * NPG * CF * sizeof(float);  // 65536
    cudaFuncSetAttribute(spmv_kernel<128>, cudaFuncAttributeMaxDynamicSharedMemorySize, SMEM);
    cudaFuncSetAttribute(spmv_kernel<32>,  cudaFuncAttributeMaxDynamicSharedMemorySize, SMEM);
    cudaFuncSetAttribute(spmv_kernel<64>,  cudaFuncAttributeMaxDynamicSharedMemorySize, SMEM);

    float* tx = nullptr; float* ha = nullptr; float* hb = nullptr;
    cudaGetSymbolAddress((void**)&tx, g_tx);
    cudaGetSymbolAddress((void**)&ha, g_ha);
    cudaGetSymbolAddress((void**)&hb, g_hb);

    deg_kernel<<<NE / 256, 256>>>(ei);                      // 0
    fill_kernel<<<NE / 256, 256>>>(ei, lam);                // 1

    spmv_kernel<128><<<dim3(16, NG), 1024, SMEM>>>(x, lam, tx);        // 2
    gemm_kernel<640, 32, 128, 2><<<NN / 128, 256>>>(tx, W1, b1, ha);   // 3 <- ncu

    spmv_kernel<32><<<dim3(4, NG), 1024, SMEM>>>(ha, lam, tx);
    gemm_kernel<160, 64, 128, 4><<<NN / 128, 256>>>(tx, W2, b2, hb);

    spmv_kernel<64><<<dim3(8, NG), 1024, SMEM>>>(hb, lam, tx);
    gemm_kernel<320, 64, 128, 4><<<NN / 128, 256>>>(tx, W3, b3, ha);

    pool_fc_kernel<<<NG, 256>>>(ha, fcW1, fcb1, fcW2, fcb2, out);

    zero_kernel<<<NN / 256, 256>>>();   // tail: reset counters for next replay
}

// round 15
// speedup vs baseline: 1.1870x; 1.1870x over previous
#include <cuda_runtime.h>
#include <cuda_bf16.h>

#define NN      65536
#define NE      1048576
#define NG      64
#define NPG     1024
#define CF      8
#define RSTRIDE 64      // edge slots per node

typedef unsigned long long ull;

__device__ int   g_deg[NN];
__device__ int   g_cnt[NN];
__device__ int   g_cur[NN];
// interleave: [(node/8)][slot/2][node%8][slot%2] -> per sub-lane, slot pair = 16B
__device__ __align__(16) int2 g_edges[(size_t)NN * RSTRIDE];
__device__ float g_tx[640ull * NN];
__device__ float g_ha[(size_t)NN * 64];
__device__ float g_hb[(size_t)NN * 64];

__device__ __forceinline__ ull pack2(float x, float y) {
    ull r; asm("mov.b64 %0, {%1, %2};" : "=l"(r) : "f"(x), "f"(y)); return r;
}
__device__ __forceinline__ void ffma2(ull& d, ull a, ull b) {
    asm("fma.rn.f32x2 %0, %1, %2, %0;" : "+l"(d) : "l"(a), "l"(b));
}
__device__ __forceinline__ void unpack2(ull v, float& x, float& y) {
    asm("mov.b64 {%0, %1}, %2;" : "=f"(x), "=f"(y) : "l"(v));
}
__device__ __forceinline__ void cp16(float* dst, const float* src) {
    unsigned int d = (unsigned int)__cvta_generic_to_shared(dst);
    asm volatile("cp.async.cg.shared.global [%0], [%1], 16;" :: "r"(d), "l"(src));
}

// ---------------- prep ----------------
// Tail-of-launch reset; __device__ arrays are zero at load, replays re-zero.
__global__ void zero_kernel() {
    int i = blockIdx.x * blockDim.x + threadIdx.x;
    if (i < NN) { g_deg[i] = 0; g_cnt[i] = 0; g_cur[i] = 0; }
}

__global__ void deg_kernel(const int* __restrict__ ei) {
    int e = blockIdx.x * blockDim.x + threadIdx.x;
    if (e >= NE) return;
    int s = ei[e], d = ei[NE + e];
    if (s != d) { atomicAdd(&g_deg[s], 1); atomicAdd(&g_cnt[d], 1); }
}

__global__ void fill_kernel(const int* __restrict__ ei,
                            const float* __restrict__ lam) {
    int e = blockIdx.x * blockDim.x + threadIdx.x;
    if (e >= NE) return;
    int s = ei[e], d = ei[NE + e];
    if (s == d) return;
    int od = g_deg[d];
    float dd = (od > 0) ? rsqrtf((float)od) : 0.0f;
    float w = -2.0f * rsqrtf((float)g_deg[s]) * dd / lam[s >> 10];
    int slot = atomicAdd(&g_cur[d], 1);
    int sloc = s & (NPG - 1);
    int eoff = (sloc << 5) | (((sloc >> 2) & 3) << 3);
    size_t idx = (size_t)(d & ~7) * RSTRIDE
               + (size_t)(slot >> 1) * 16 + (d & 7) * 2 + (slot & 1);
    g_edges[idx] = make_int2(eoff, __float_as_int(w));
}

// ---------------- Chebyshev recurrence (unchanged from R11) ----------------
template<int F>
__global__ void __launch_bounds__(1024, 2)
spmv_kernel(const float* __restrict__ hin, const float* __restrict__ lam,
            float* __restrict__ txout) {
    extern __shared__ float sm[];
    float* buf0 = sm;                   // [1024][8] swizzled
    float* buf1 = sm + NPG * 8;

    const int g = blockIdx.y, cb = blockIdx.x * CF, t = threadIdx.x;
    const int gbase = g * NPG;
    const float diag = 2.0f / lam[g] - 1.0f;

    const float* hp = hin + (size_t)gbase * F + cb;
    #pragma unroll
    for (int r = 0; r < CF; r++) {
        int i = r * 1024 + t;
        int row = i >> 3, f = i & 7;
        int sw = ((f >> 1) ^ ((row >> 2) & 3)) * 2 + (f & 1);
        buf0[row * 8 + sw] = hp[row * F + f];
    }
    __syncthreads();

    {
        int s_t = (t >> 2) & 3;
        #pragma unroll
        for (int f = 0; f < CF; f++) {
            int sw = ((f >> 1) ^ s_t) * 2 + (f & 1);
            txout[(size_t)(cb + f) * NN + gbase + t] = buf0[t * 8 + sw];
        }
    }

    const int lane = t & 31, warp = t >> 5;
    const int fp8 = (lane & 3) * 8;
    const int sub = lane >> 2;
    int v = g_cnt[gbase + warp * 32 + lane];
    v = max(v, __shfl_xor_sync(0xffffffffu, v, 1));
    v = max(v, __shfl_xor_sync(0xffffffffu, v, 2));
    v = max(v, __shfl_xor_sync(0xffffffffu, v, 4));

    float* cur = buf0; float* oth = buf1;
    for (int k = 1; k < 5; k++) {
        const char* curb = (const char*)cur;
        #pragma unroll 1
        for (int p = 0; p < 4; p++) {
            const int gdeg = __shfl_sync(0xffffffffu, v, p * 8);
            const int node8 = warp * 32 + p * 8;
            const char* ebase =
                (const char*)(g_edges + (size_t)(gbase + node8) * RSTRIDE) + sub * 16;
            float ax = 0.0f, ay = 0.0f;
            #pragma unroll 1
            for (int i = 0; i < gdeg; i += 4) {
                int4 E0 = *(const int4*)(ebase + (size_t)i * 64);
                int4 E1 = *(const int4*)(ebase + (size_t)i * 64 + 128);
                float2 v0 = *(const float2*)(curb + (E0.x ^ fp8));
                float2 v1 = *(const float2*)(curb + (E0.z ^ fp8));
                float2 v2 = *(const float2*)(curb + (E1.x ^ fp8));
                float2 v3 = *(const float2*)(curb + (E1.z ^ fp8));
                float w0 = __int_as_float(E0.y), w1 = __int_as_float(E0.w);
                float w2 = __int_as_float(E1.y), w3 = __int_as_float(E1.w);
                ax = fmaf(w0, v0.x, ax); ay = fmaf(w0, v0.y, ay);
                ax = fmaf(w1, v1.x, ax); ay = fmaf(w1, v1.y, ay);
                ax = fmaf(w2, v2.x, ax); ay = fmaf(w2, v2.y, ay);
                ax = fmaf(w3, v3.x, ax); ay = fmaf(w3, v3.y, ay);
            }
            const int dloc = node8 + sub;
            const int swb = fp8 ^ (((dloc >> 2) & 3) << 3);
            float2 c = *(const float2*)((const char*)cur + dloc * 32 + swb);
            float lx = fmaf(diag, c.x, ax);
            float ly = fmaf(diag, c.y, ay);
            float2* op = (float2*)((char*)oth + dloc * 32 + swb);
            if (k > 1) { float2 o = *op; lx = 2.0f * lx - o.x; ly = 2.0f * ly - o.y; }
            *op = make_float2(lx, ly);
        }
        __syncthreads();
        int s_t = (t >> 2) & 3;
        #pragma unroll
        for (int f = 0; f < CF; f++) {
            int sw = ((f >> 1) ^ s_t) * 2 + (f & 1);
            txout[(size_t)(k * F + cb + f) * NN + gbase + t] = oth[t * 8 + sw];
        }
        float* tmp = cur; cur = oth; oth = tmp;
        __syncthreads();
    }
}

// ---------------- GEMM v4: TM=8 tile + cp.async double buffering ----------------
// out = relu(A^T W + b); A:[K][NN], W:[K][N]. threads = (MT/8)*(N/8).
template<int K, int N, int MT>
__global__ void __launch_bounds__((MT / 8) * (N / 8))
gemm_kernel(const float* __restrict__ A, const float* __restrict__ W,
            const float* __restrict__ bias, float* __restrict__ out) {
    constexpr int NJG = N / 8;
    constexpr int MG  = MT / 8;
    constexpr int T   = MG * NJG;
    constexpr int S   = K / 16;
    __shared__ __align__(16) float As[2][16 * MT];
    __shared__ __align__(16) float Ws[2][16 * N];

    const int t = threadIdx.x;
    const int jg = t % NJG, mg = t / NJG;
    const int m0 = blockIdx.x * MT;

    auto prefetch = [&](int buf, int k0) {
        for (int i = t * 4; i < 16 * MT; i += T * 4)
            cp16(&As[buf][i], &A[(size_t)(k0 + i / MT) * NN + m0 + (i % MT)]);
        for (int i = t * 4; i < 16 * N; i += T * 4)
            cp16(&Ws[buf][i], &W[(size_t)k0 * N + i]);
    };

    prefetch(0, 0);
    asm volatile("cp.async.commit_group;");

    ull acc[8][4];
    #pragma unroll
    for (int a = 0; a < 8; a++)
        #pragma unroll
        for (int b = 0; b < 4; b++) acc[a][b] = 0ULL;

    int buf = 0;
    for (int s = 0; s < S; s++) {
        if (s + 1 < S) prefetch(buf ^ 1, (s + 1) * 16);
        asm volatile("cp.async.commit_group;");
        asm volatile("cp.async.wait_group 1;");
        __syncthreads();
        #pragma unroll
        for (int kk = 0; kk < 16; kk++) {
            const float4* ap = (const float4*)&As[buf][kk * MT + mg * 8];
            float4 a0 = ap[0], a1 = ap[1];
            const ull* wr = (const ull*)&Ws[buf][kk * N + jg * 8];
            ull w0 = wr[0], w1 = wr[1], w2 = wr[2], w3 = wr[3];
            float av[8] = {a0.x, a0.y, a0.z, a0.w, a1.x, a1.y, a1.z, a1.w};
            #pragma unroll
            for (int tt = 0; tt < 8; tt++) {
                ull ab = pack2(av[tt], av[tt]);
                ffma2(acc[tt][0], ab, w0);
                ffma2(acc[tt][1], ab, w1);
                ffma2(acc[tt][2], ab, w2);
                ffma2(acc[tt][3], ab, w3);
            }
        }
        __syncthreads();   // all reads of buf done before it is re-prefetched
        buf ^= 1;
    }

    #pragma unroll
    for (int tt = 0; tt < 8; tt++) {
        size_t node = m0 + mg * 8 + tt;
        #pragma unroll
        for (int p = 0; p < 4; p++) {
            float x, y; unpack2(acc[tt][p], x, y);
            int j = jg * 8 + 2 * p;
            x = fmaxf(x + bias[j], 0.0f);
            y = fmaxf(y + bias[j + 1], 0.0f);
            *reinterpret_cast<float2*>(&out[node * N + j]) = make_float2(x, y);
        }
    }
}

// ---------------- pool + FC ----------------
__global__ void pool_fc_kernel(const float* __restrict__ h,
                               const float* __restrict__ fcW1, const float* __restrict__ fcb1,
                               const float* __restrict__ fcW2, const float* __restrict__ fcb2,
                               float* __restrict__ out) {
    __shared__ float red[256];
    __shared__ float pool[64];
    __shared__ float z1[10];
    int g = blockIdx.x, t = threadIdx.x;
    int f = t & 63, part = t >> 6;
    float s = 0.0f;
    for (int n = part; n < NPG; n += 4)
        s += h[(size_t)(g * NPG + n) * 64 + f];
    red[t] = s;
    __syncthreads();
    if (part == 0)
        pool[f] = (red[f] + red[64 + f] + red[128 + f] + red[192 + f]) * (1.0f / NPG);
    __syncthreads();
    if (t < 10) {
        float z = fcb1[t];
        for (int i = 0; i < 64; i++) z += pool[i] * fcW1[i * 10 + t];
        z1[t] = fmaxf(z, 0.0f);
    }
    __syncthreads();
    if (t < 10) {
        float z = fcb2[t];
        for (int j = 0; j < 10; j++) z += z1[j] * fcW2[j * 10 + t];
        out[g * 10 + t] = z;
    }
}

// ---------------- launch ----------------
extern "C" void kernel_launch(void* const* d_in, const int* in_sizes, int n_in,
                              void* d_out, int out_size) {
    const float* x     = (const float*)d_in[0];
    const int*   ei    = (const int*)d_in[1];
    const float* lam   = (const float*)d_in[3];
    const float* W1 = (const float*)d_in[4];  const float* b1 = (const float*)d_in[5];
    const float* W2 = (const float*)d_in[6];  const float* b2 = (const float*)d_in[7];
    const float* W3 = (const float*)d_in[8];  const float* b3 = (const float*)d_in[9];
    const float* fcW1 = (const float*)d_in[10]; const float* fcb1 = (const float*)d_in[11];
    const float* fcW2 = (const float*)d_in[12]; const float* fcb2 = (const float*)d_in[13];
    float* out = (float*)d_out;

    const int SMEM = 2 * NPG * CF * sizeof(float);  // 65536
    cudaFuncSetAttribute(spmv_kernel<128>, cudaFuncAttributeMaxDynamicSharedMemorySize, SMEM);
    cudaFuncSetAttribute(spmv_kernel<32>,  cudaFuncAttributeMaxDynamicSharedMemorySize, SMEM);
    cudaFuncSetAttribute(spmv_kernel<64>,  cudaFuncAttributeMaxDynamicSharedMemorySize, SMEM);

    float* tx = nullptr; float* ha = nullptr; float* hb = nullptr;
    cudaGetSymbolAddress((void**)&tx, g_tx);
    cudaGetSymbolAddress((void**)&ha, g_ha);
    cudaGetSymbolAddress((void**)&hb, g_hb);

    deg_kernel<<<NE / 256, 256>>>(ei);                      // 0
    fill_kernel<<<NE / 256, 256>>>(ei, lam);                // 1

    spmv_kernel<128><<<dim3(16, NG), 1024, SMEM>>>(x, lam, tx);     // 2
    gemm_kernel<640, 32, 256><<<NN / 256, 128>>>(tx, W1, b1, ha);   // 3 <- ncu

    spmv_kernel<32><<<dim3(4, NG), 1024, SMEM>>>(ha, lam, tx);
    gemm_kernel<160, 64, 256><<<NN / 256, 256>>>(tx, W2, b2, hb);

    spmv_kernel<64><<<dim3(8, NG), 1024, SMEM>>>(hb, lam, tx);
    gemm_kernel<320, 64, 256><<<NN / 256, 256>>>(tx, W3, b3, ha);

    pool_fc_kernel<<<NG, 256>>>(ha, fcW1, fcb1, fcW2, fcb2, out);

    zero_kernel<<<NN / 256, 256>>>();   // tail: reset counters for next replay
}